// round 4
// baseline (speedup 1.0000x reference)
#include <cuda_runtime.h>
#include <cuda_bf16.h>

// Problem constants
#define B_    64
#define C_    2048
#define HW_   576
#define HW4_  144          // HW_ / 4 float4s per channel row
#define NBLK  16           // k1 grid.x  (128 channels per block)
#define NSUB  64           // partial sub-chunks per (t,b): NBLK * 4
#define CPS   32           // channels per (block, csub) = 128/4

// Scratch (allocation-free rule: __device__ globals)
__device__ float4       g_part4[2][B_][NSUB][HW4_]; // per-subchunk partial lum
__device__ float        g_lum_v[B_][HW_];           // lum_v row-major
__device__ float        g_lum_iT[HW_][B_];          // lum_i TRANSPOSED
__device__ double       g_sum;                      // masked mse accumulator
__device__ int          g_cnt;                      // masked pair count
__device__ unsigned int g_ticket;                   // last-block election

// ---------------------------------------------------------------------------
// Kernel 1: streaming sum-of-squares, float4 loads (LDG.128).
// grid = (NBLK, B, 2), block = 576.
// Thread tid -> q = tid%144 (float4 pixel group), csub = tid/144 (0..3).
// csub handles 32 contiguous channels; warp reads contiguous 512B runs.
// Each thread stores ONE float4 partial -> no intra-block reduce.
// ---------------------------------------------------------------------------
__global__ void __launch_bounds__(576, 3)
k_lum_partial(const float* __restrict__ fv, const float* __restrict__ fi) {
    const int blk  = blockIdx.x;
    const int b    = blockIdx.y;
    const int t    = blockIdx.z;
    const int tid  = threadIdx.x;
    const int q    = tid % HW4_;
    const int csub = tid / HW4_;

    const float* __restrict__ f = (t == 0) ? fv : fi;
    // tile: 128 channels starting at blk*128
    const float4* __restrict__ p4 = (const float4*)
        (f + ((size_t)b * C_ + (size_t)blk * 128) * HW_);
    const float4* __restrict__ base = p4 + ((size_t)csub * CPS) * HW4_ + q;

    float ax = 0.f, ay = 0.f, az = 0.f, aw = 0.f;
#pragma unroll 8
    for (int it = 0; it < CPS; ++it) {
        float4 x = base[(size_t)it * HW4_];
        ax = fmaf(x.x, x.x, ax);
        ay = fmaf(x.y, x.y, ay);
        az = fmaf(x.z, x.z, az);
        aw = fmaf(x.w, x.w, aw);
    }
    g_part4[t][b][blk * 4 + csub][q] = make_float4(ax, ay, az, aw);
}

// ---------------------------------------------------------------------------
// Kernel 2: fold 64 sub-chunk partials; lum_v row-major, lum_i transposed.
// Also zeroes g_sum / g_cnt (stream-ordered before k_pair).
// grid = (B, 2), block = 576: q = tid%144, g = tid/144 folds 16 chunks.
// ---------------------------------------------------------------------------
__global__ void k_lum_reduce() {
    const int b   = blockIdx.x;
    const int t   = blockIdx.y;
    const int tid = threadIdx.x;
    const int q   = tid % HW4_;
    const int g   = tid / HW4_;

    if (b == 0 && t == 0 && tid == 0) { g_sum = 0.0; g_cnt = 0; }

    float4 s = make_float4(0.f, 0.f, 0.f, 0.f);
#pragma unroll
    for (int c = g * 16; c < g * 16 + 16; ++c) {
        float4 x = g_part4[t][b][c][q];
        s.x += x.x; s.y += x.y; s.z += x.z; s.w += x.w;
    }

    __shared__ float4 sh[4][HW4_];
    sh[g][q] = s;
    __syncthreads();

    if (g == 0) {
        float4 a = sh[0][q], c1 = sh[1][q], c2 = sh[2][q], c3 = sh[3][q];
        a.x += c1.x + c2.x + c3.x;
        a.y += c1.y + c2.y + c3.y;
        a.z += c1.z + c2.z + c3.z;
        a.w += c1.w + c2.w + c3.w;
        if (t == 0) {
            ((float4*)g_lum_v[b])[q] = a;
        } else {
            g_lum_iT[4 * q + 0][b] = a.x;
            g_lum_iT[4 * q + 1][b] = a.y;
            g_lum_iT[4 * q + 2][b] = a.z;
            g_lum_iT[4 * q + 3][b] = a.w;
        }
    }
}

// ---------------------------------------------------------------------------
// Kernel 3: pairwise MSE + mask + reduce + FINALIZE. block = i, thread = j.
// fp32 inner chunks (32 terms) flushed to double accumulators.
// Last block (ticket) computes final scalar. Labels are int32 (JAX x64 off).
// grid = 64, block = 64.
// ---------------------------------------------------------------------------
__global__ void k_pair(const int* __restrict__ labels,
                       float* __restrict__ out) {
    const int i = blockIdx.x;
    const int j = threadIdx.x;   // 0..63

    __shared__ float  s_lv[HW_];
    __shared__ double s_red[64];

    for (int p = j; p < HW_; p += 64) s_lv[p] = g_lum_v[i][p];
    __syncthreads();

    // sv2 = sum_p lv^2
    {
        float pv = 0.0f;
        for (int p = j; p < HW_; p += 64) {
            float v = s_lv[p];
            pv = fmaf(v, v, pv);
        }
        s_red[j] = (double)pv;
    }
    __syncthreads();
    for (int s = 32; s > 0; s >>= 1) {
        if (j < s) s_red[j] += s_red[j + s];
        __syncthreads();
    }
    const double sv2 = s_red[0];
    __syncthreads();

    // cross = sum_p lv*li,  si2 = sum_p li^2 (coalesced via transpose)
    double crossd = 0.0, si2d = 0.0;
    for (int p0 = 0; p0 < HW_; p0 += 32) {
        float cf = 0.0f, sf = 0.0f;
#pragma unroll
        for (int k = 0; k < 32; ++k) {
            int   p  = p0 + k;
            float lv = s_lv[p];
            float li = g_lum_iT[p][j];
            cf = fmaf(lv, li, cf);
            sf = fmaf(li, li, sf);
        }
        crossd += (double)cf;
        si2d   += (double)sf;
    }

    const double mse = (sv2 + si2d - 2.0 * crossd) / (double)HW_;

    const bool m = (labels[i] == labels[j]) && (i != j);
    const int cnt_i = __syncthreads_count(m);   // also a barrier

    s_red[j] = m ? mse : 0.0;
    __syncthreads();
    for (int s = 32; s > 0; s >>= 1) {
        if (j < s) s_red[j] += s_red[j + s];
        __syncthreads();
    }

    if (j == 0) {
        atomicAdd(&g_sum, s_red[0]);
        atomicAdd(&g_cnt, cnt_i);
        __threadfence();
        unsigned t = atomicAdd(&g_ticket, 1u);
        if (t == gridDim.x - 1) {
            double total = atomicAdd(&g_sum, 0.0);   // atomic read
            int    cnt   = atomicAdd(&g_cnt, 0);
            out[0] = (cnt > 0) ? (float)(total / (double)cnt) : 0.0f;
            g_ticket = 0;                            // reset for next replay
        }
    }
}

extern "C" void kernel_launch(void* const* d_in, const int* in_sizes, int n_in,
                              void* d_out, int out_size) {
    const float* fv     = (const float*)d_in[0];
    const float* fi     = (const float*)d_in[1];
    const int*   labels = (const int*)d_in[2];
    float*       out    = (float*)d_out;

    k_lum_partial<<<dim3(NBLK, B_, 2), 576>>>(fv, fi);
    k_lum_reduce<<<dim3(B_, 2), 576>>>();
    k_pair<<<B_, 64>>>(labels, out);
}